// round 1
// baseline (speedup 1.0000x reference)
#include <cuda_runtime.h>

// Problem constants
#define TT 8
#define HH 64
#define WW 64
#define CC 256
#define HEADS 8
#define HDIM 32
#define WS 7
#define NNB 147                      // 3 * 49
#define NPIX (TT*HH*WW)              // 32768
#define QKCOLS (2*CC)                // 512
#define ATTN_ELEMS (HEADS*TT*HH*WW*NNB)   // 38,535,168
#define PER_HEAD_FLOW (TT*HH*WW*NNB*3)    // 14,450,688

// Scratch: projected q|k, layout [pix][512] (first 256 = q all heads, last 256 = k)
__device__ float g_qk[(size_t)NPIX * QKCOLS];

// ---------------- helpers ----------------
__device__ __forceinline__ int reflect_idx(int idx) {
    // period = 2*(64-1) = 126 ; python-style nonneg mod then fold
    int m = idx % 126;
    if (m < 0) m += 126;
    return (m > 63) ? (126 - m) : m;
}

__device__ __forceinline__ unsigned long long pk2(float lo, float hi) {
    unsigned long long r;
    asm("mov.b64 %0, {%1,%2};" : "=l"(r) : "f"(lo), "f"(hi));
    return r;
}
__device__ __forceinline__ float2 unpk2(unsigned long long v) {
    float2 r;
    asm("mov.b64 {%0,%1}, %2;" : "=f"(r.x), "=f"(r.y) : "l"(v));
    return r;
}
__device__ __forceinline__ unsigned long long fma2(unsigned long long a,
                                                   unsigned long long b,
                                                   unsigned long long c) {
    unsigned long long d;
    asm("fma.rn.f32x2 %0, %1, %2, %3;" : "=l"(d) : "l"(a), "l"(b), "l"(c));
    return d;
}

// ---------------- Kernel 1: qk = x @ W_qk^T (fp32, f32x2 FFMA) ----------------
// C[m][n] = sum_k A[m][k] * W[n][k];  M=32768, N=512, K=256
#define BM 128
#define BN 128
#define BK 16
#define SST 132   // smem row stride (multiple of 4 for LDS.128, odd/4 to dodge conflicts)

__global__ __launch_bounds__(256, 2)
void gemm_qk(const float* __restrict__ A, const float* __restrict__ Wm) {
    __shared__ float As[BK * SST];
    __shared__ float Bs[BK * SST];

    const int m0 = blockIdx.y * BM;
    const int n0 = blockIdx.x * BN;
    const int tid = threadIdx.x;
    const int tx = tid & 15;     // n direction
    const int ty = tid >> 4;     // m direction

    unsigned long long acc[8][4];
#pragma unroll
    for (int i = 0; i < 8; i++)
#pragma unroll
        for (int j = 0; j < 4; j++) acc[i][j] = 0ULL;

    for (int k0 = 0; k0 < CC; k0 += BK) {
        // cooperative load + transpose into As[k][m], Bs[k][n]
#pragma unroll
        for (int i = 0; i < 2; i++) {
            int id = tid + 256 * i;          // 0..511
            int row = id >> 2;               // 0..127
            int cc4 = (id & 3) << 2;         // 0,4,8,12
            float4 av = *(const float4*)(A + (size_t)(m0 + row) * CC + k0 + cc4);
            As[(cc4 + 0) * SST + row] = av.x;
            As[(cc4 + 1) * SST + row] = av.y;
            As[(cc4 + 2) * SST + row] = av.z;
            As[(cc4 + 3) * SST + row] = av.w;
            float4 bv = *(const float4*)(Wm + (size_t)(n0 + row) * CC + k0 + cc4);
            Bs[(cc4 + 0) * SST + row] = bv.x;
            Bs[(cc4 + 1) * SST + row] = bv.y;
            Bs[(cc4 + 2) * SST + row] = bv.z;
            Bs[(cc4 + 3) * SST + row] = bv.w;
        }
        __syncthreads();

#pragma unroll
        for (int kk = 0; kk < BK; kk++) {
            const float4 a0 = *(const float4*)&As[kk * SST + ty * 8];
            const float4 a1 = *(const float4*)&As[kk * SST + ty * 8 + 4];
            const float4 b0 = *(const float4*)&Bs[kk * SST + tx * 8];
            const float4 b1 = *(const float4*)&Bs[kk * SST + tx * 8 + 4];
            unsigned long long bp[4] = {pk2(b0.x, b0.y), pk2(b0.z, b0.w),
                                        pk2(b1.x, b1.y), pk2(b1.z, b1.w)};
            float av[8] = {a0.x, a0.y, a0.z, a0.w, a1.x, a1.y, a1.z, a1.w};
#pragma unroll
            for (int i = 0; i < 8; i++) {
                unsigned long long ap = pk2(av[i], av[i]);
#pragma unroll
                for (int j = 0; j < 4; j++) acc[i][j] = fma2(ap, bp[j], acc[i][j]);
            }
        }
        __syncthreads();
    }

#pragma unroll
    for (int i = 0; i < 8; i++) {
        float2 c0 = unpk2(acc[i][0]);
        float2 c1 = unpk2(acc[i][1]);
        float2 c2 = unpk2(acc[i][2]);
        float2 c3 = unpk2(acc[i][3]);
        float* dst = g_qk + (size_t)(m0 + ty * 8 + i) * QKCOLS + n0 + tx * 8;
        *(float4*)dst       = make_float4(c0.x, c0.y, c1.x, c1.y);
        *(float4*)(dst + 4) = make_float4(c2.x, c2.y, c3.x, c3.y);
    }
}

// ---------------- Kernel 2: attention scores ----------------
// warp per pixel (all 8 heads), lanes split the 1KB k-row; 4x2 pixel tile per block
__global__ __launch_bounds__(256)
void attn_kernel(const float* __restrict__ flows, float* __restrict__ out) {
    __shared__ float sbuf[8][HEADS * NNB];   // per-warp score buffer (8*1176 floats)

    const int tidx = threadIdx.x;
    const int wid = tidx >> 5;
    const int lane = tidx & 31;

    const int t = blockIdx.z;
    const int h = blockIdx.y * 4 + (wid >> 1);
    const int w = blockIdx.x * 2 + (wid & 1);
    const int hw = h * WW + w;
    const int pix = t * (HH * WW) + hw;

    const float* qrow = g_qk + (size_t)pix * QKCOLS;
    const float4 qa = *(const float4*)(qrow + lane * 4);         // head = lane>>3
    const float4 qb = *(const float4*)(qrow + 128 + lane * 4);   // head = 4 + (lane>>3)

    const int tp1 = (t + 1 < TT) ? t + 1 : t - 2;
    const int tp2 = (t - 1 >= 0) ? t - 1 : t + 2;

    const float f10 = flows[(4 * t + 0) * 4096 + hw];
    const float f11 = flows[(4 * t + 1) * 4096 + hw];
    const float f20 = flows[(4 * t + 2) * 4096 + hw];
    const float f21 = flows[(4 * t + 3) * 4096 + hw];

    const int tpr[3] = {t, tp1, tp2};
    const int dii[3] = {0, __float2int_rn(f10), __float2int_rn(f20)};
    const int djj[3] = {0, __float2int_rn(f11), __float2int_rn(f21)};

    float* srow = sbuf[wid];

#pragma unroll
    for (int s = 0; s < 3; s++) {
        const float* tslice = g_qk + (size_t)tpr[s] * (HH * WW) * QKCOLS + CC; // k half
        const int ci = h + dii[s];
        const int cj = w + djj[s];
        int ljo[WS];
#pragma unroll
        for (int b = 0; b < WS; b++) ljo[b] = reflect_idx(cj + b - 3) * QKCOLS;

        for (int a = 0; a < WS; a++) {
            const int li = reflect_idx(ci + a - 3);
            const float* rbase = tslice + (size_t)li * WW * QKCOLS;
#pragma unroll
            for (int b = 0; b < WS; b++) {
                const float* kp = rbase + ljo[b];
                const float4 k0 = *(const float4*)(kp + lane * 4);
                const float4 k1 = *(const float4*)(kp + 128 + lane * 4);
                float pA = fmaf(qa.x, k0.x, fmaf(qa.y, k0.y, fmaf(qa.z, k0.z, qa.w * k0.w)));
                float pB = fmaf(qb.x, k1.x, fmaf(qb.y, k1.y, fmaf(qb.z, k1.z, qb.w * k1.w)));
#pragma unroll
                for (int o = 4; o >= 1; o >>= 1) {
                    pA += __shfl_xor_sync(0xffffffffu, pA, o);
                    pB += __shfl_xor_sync(0xffffffffu, pB, o);
                }
                if ((lane & 7) == 0) {
                    const int n = s * 49 + a * 7 + b;
                    const int hg = lane >> 3;
                    srow[hg * NNB + n] = pA;
                    srow[(hg + 4) * NNB + n] = pB;
                }
            }
        }
    }
    __syncwarp();

    const float scale = 0.17677669529663687f;   // 32^-0.5
#pragma unroll
    for (int head = 0; head < HEADS; head++) {
        size_t obase = ((size_t)(head * TT + t) * (HH * WW) + hw) * (size_t)NNB;
        for (int i = lane; i < NNB; i += 32)
            out[obase + i] = srow[head * NNB + i] * scale;
    }
}

// ---------------- Kernel 3: flows_k writer ----------------
// block = 8 pixels: compute 8*441 values once into smem, replicate x8 heads coalesced
__global__ __launch_bounds__(256)
void flowsk_kernel(const float* __restrict__ flows, float* __restrict__ outF) {
    __shared__ float sbuf[8 * NNB * 3];   // 3528 floats

    const int pix0 = blockIdx.x * 8;
    const int tid = threadIdx.x;

    for (int e = tid; e < 8 * NNB * 3; e += 256) {
        const int lp = e / (NNB * 3);
        const int r = e - lp * (NNB * 3);
        const int n = r / 3;
        const int c = r - n * 3;
        const int pix = pix0 + lp;
        const int t = pix >> 12;
        const int hw = pix & 4095;
        const int h = hw >> 6;
        const int w = hw & 63;

        const int s = n / 49;
        const int wn = n - s * 49;
        const int a = wn / 7;
        const int b = wn - a * 7;

        int dt, di, dj;
        if (s == 0) {
            dt = 0; di = 0; dj = 0;
        } else if (s == 1) {
            dt = (t + 1 < TT) ? 1 : -2;
            di = __float2int_rn(flows[(4 * t + 0) * 4096 + hw]);
            dj = __float2int_rn(flows[(4 * t + 1) * 4096 + hw]);
        } else {
            dt = (t - 1 >= 0) ? -1 : 2;
            di = __float2int_rn(flows[(4 * t + 2) * 4096 + hw]);
            dj = __float2int_rn(flows[(4 * t + 3) * 4096 + hw]);
        }

        int v;
        if (c == 0)      v = dt;
        else if (c == 1) v = reflect_idx(h + di + a - 3) - h;
        else             v = reflect_idx(w + dj + b - 3) - w;
        sbuf[e] = (float)v;
    }
    __syncthreads();

    const float4* s4 = (const float4*)sbuf;
    const int nv4 = (8 * NNB * 3) / 4;   // 882
#pragma unroll
    for (int head = 0; head < HEADS; head++) {
        float4* dst = (float4*)(outF + (size_t)head * PER_HEAD_FLOW + (size_t)pix0 * (NNB * 3));
        for (int i = tid; i < nv4; i += 256) dst[i] = s4[i];
    }
}

// ---------------- launch ----------------
extern "C" void kernel_launch(void* const* d_in, const int* in_sizes, int n_in,
                              void* d_out, int out_size) {
    const float* x     = (const float*)d_in[0];
    const float* flows = (const float*)d_in[1];
    const float* Wm    = (const float*)d_in[2];
    float* out = (float*)d_out;

    // 1) projection GEMM -> g_qk
    gemm_qk<<<dim3(QKCOLS / BN, NPIX / BM), 256>>>(x, Wm);

    // 2) attention scores -> out[0 .. ATTN_ELEMS)
    attn_kernel<<<dim3(WW / 2, HH / 4, TT), 256>>>(flows, out);

    // 3) neighbor offsets -> out[ATTN_ELEMS .. )
    if ((long long)out_size >= (long long)ATTN_ELEMS + (long long)HEADS * PER_HEAD_FLOW) {
        flowsk_kernel<<<NPIX / 8, 256>>>(flows, out + ATTN_ELEMS);
    }
}

// round 2
// speedup vs baseline: 2.1925x; 2.1925x over previous
#include <cuda_runtime.h>
#include <cuda_fp16.h>

// Problem constants
#define TT 8
#define HH 64
#define WW 64
#define CC 256
#define HEADS 8
#define HDIM 32
#define WS 7
#define NNB 147                      // 3 * 49
#define NPIX (TT*HH*WW)              // 32768
#define ATTN_ELEMS (HEADS*TT*HH*WW*NNB)   // 38,535,168
#define PER_HEAD_FLOW (TT*HH*WW*NNB*3)    // 14,450,688

// Scratch: q in fp32 [pix][256], k in fp16 [pix][256]
__device__ float  g_q [(size_t)NPIX * CC];
__device__ __half g_kh[(size_t)NPIX * CC];

// ---------------- helpers ----------------
__device__ __forceinline__ int reflect_idx(int idx) {
    int m = idx % 126;                 // period = 2*(64-1)
    if (m < 0) m += 126;
    return (m > 63) ? (126 - m) : m;
}

__device__ __forceinline__ unsigned long long pk2(float lo, float hi) {
    unsigned long long r;
    asm("mov.b64 %0, {%1,%2};" : "=l"(r) : "f"(lo), "f"(hi));
    return r;
}
__device__ __forceinline__ float2 unpk2(unsigned long long v) {
    float2 r;
    asm("mov.b64 {%0,%1}, %2;" : "=f"(r.x), "=f"(r.y) : "l"(v));
    return r;
}
__device__ __forceinline__ unsigned long long fma2(unsigned long long a,
                                                   unsigned long long b,
                                                   unsigned long long c) {
    unsigned long long d;
    asm("fma.rn.f32x2 %0, %1, %2, %3;" : "=l"(d) : "l"(a), "l"(b), "l"(c));
    return d;
}

// ---------------- Kernel 1: qk = x @ W_qk^T (fp32 f32x2, double-buffered) ----
// C[m][n] = sum_k A[m][k]*W[n][k]; M=32768, N=512, K=256
// n<256 -> g_q fp32 ; n>=256 -> g_kh fp16
#define BM 128
#define BN 128
#define BK 16
#define NIT (CC/BK)
#define SST 132

__global__ __launch_bounds__(256, 2)
void gemm_qk(const float* __restrict__ A, const float* __restrict__ Wm) {
    __shared__ float As[2][BK * SST];
    __shared__ float Bs[2][BK * SST];

    const int m0 = blockIdx.y * BM;
    const int n0 = blockIdx.x * BN;
    const int tid = threadIdx.x;
    const int tx = tid & 15;
    const int ty = tid >> 4;

    // loader index precompute (each thread: one float4 of A and B per half-id)
    int lrow[2], lc4[2];
#pragma unroll
    for (int i = 0; i < 2; i++) {
        int id = tid + 256 * i;
        lrow[i] = id >> 2;
        lc4[i] = (id & 3) << 2;
    }

    unsigned long long acc[8][4];
#pragma unroll
    for (int i = 0; i < 8; i++)
#pragma unroll
        for (int j = 0; j < 4; j++) acc[i][j] = 0ULL;

    float4 av[2], bv[2];
#pragma unroll
    for (int i = 0; i < 2; i++) {
        av[i] = *(const float4*)(A  + (size_t)(m0 + lrow[i]) * CC + lc4[i]);
        bv[i] = *(const float4*)(Wm + (size_t)(n0 + lrow[i]) * CC + lc4[i]);
    }
#pragma unroll
    for (int i = 0; i < 2; i++) {
        As[0][(lc4[i] + 0) * SST + lrow[i]] = av[i].x;
        As[0][(lc4[i] + 1) * SST + lrow[i]] = av[i].y;
        As[0][(lc4[i] + 2) * SST + lrow[i]] = av[i].z;
        As[0][(lc4[i] + 3) * SST + lrow[i]] = av[i].w;
        Bs[0][(lc4[i] + 0) * SST + lrow[i]] = bv[i].x;
        Bs[0][(lc4[i] + 1) * SST + lrow[i]] = bv[i].y;
        Bs[0][(lc4[i] + 2) * SST + lrow[i]] = bv[i].z;
        Bs[0][(lc4[i] + 3) * SST + lrow[i]] = bv[i].w;
    }
    __syncthreads();

    for (int it = 0; it < NIT; it++) {
        const int buf = it & 1;
        if (it + 1 < NIT) {
            const int k0 = (it + 1) * BK;
#pragma unroll
            for (int i = 0; i < 2; i++) {
                av[i] = *(const float4*)(A  + (size_t)(m0 + lrow[i]) * CC + k0 + lc4[i]);
                bv[i] = *(const float4*)(Wm + (size_t)(n0 + lrow[i]) * CC + k0 + lc4[i]);
            }
        }

#pragma unroll
        for (int kk = 0; kk < BK; kk++) {
            const float4 a0 = *(const float4*)&As[buf][kk * SST + ty * 8];
            const float4 a1 = *(const float4*)&As[buf][kk * SST + ty * 8 + 4];
            const float4 b0 = *(const float4*)&Bs[buf][kk * SST + tx * 8];
            const float4 b1 = *(const float4*)&Bs[buf][kk * SST + tx * 8 + 4];
            unsigned long long bp[4] = {pk2(b0.x, b0.y), pk2(b0.z, b0.w),
                                        pk2(b1.x, b1.y), pk2(b1.z, b1.w)};
            float a[8] = {a0.x, a0.y, a0.z, a0.w, a1.x, a1.y, a1.z, a1.w};
#pragma unroll
            for (int i = 0; i < 8; i++) {
                unsigned long long ap = pk2(a[i], a[i]);
#pragma unroll
                for (int j = 0; j < 4; j++) acc[i][j] = fma2(ap, bp[j], acc[i][j]);
            }
        }

        if (it + 1 < NIT) {
            const int nb = buf ^ 1;
#pragma unroll
            for (int i = 0; i < 2; i++) {
                As[nb][(lc4[i] + 0) * SST + lrow[i]] = av[i].x;
                As[nb][(lc4[i] + 1) * SST + lrow[i]] = av[i].y;
                As[nb][(lc4[i] + 2) * SST + lrow[i]] = av[i].z;
                As[nb][(lc4[i] + 3) * SST + lrow[i]] = av[i].w;
                Bs[nb][(lc4[i] + 0) * SST + lrow[i]] = bv[i].x;
                Bs[nb][(lc4[i] + 1) * SST + lrow[i]] = bv[i].y;
                Bs[nb][(lc4[i] + 2) * SST + lrow[i]] = bv[i].z;
                Bs[nb][(lc4[i] + 3) * SST + lrow[i]] = bv[i].w;
            }
        }
        __syncthreads();
    }

    // epilogue: n<256 -> fp32 q ; n>=256 -> fp16 k
    const bool is_k = (n0 >= CC);
#pragma unroll
    for (int i = 0; i < 8; i++) {
        float2 c0 = unpk2(acc[i][0]);
        float2 c1 = unpk2(acc[i][1]);
        float2 c2 = unpk2(acc[i][2]);
        float2 c3 = unpk2(acc[i][3]);
        const int row = m0 + ty * 8 + i;
        const int col = n0 + tx * 8;
        if (!is_k) {
            float* dst = g_q + (size_t)row * CC + col;
            *(float4*)dst       = make_float4(c0.x, c0.y, c1.x, c1.y);
            *(float4*)(dst + 4) = make_float4(c2.x, c2.y, c3.x, c3.y);
        } else {
            __half2 h[4];
            h[0] = __floats2half2_rn(c0.x, c0.y);
            h[1] = __floats2half2_rn(c1.x, c1.y);
            h[2] = __floats2half2_rn(c2.x, c2.y);
            h[3] = __floats2half2_rn(c3.x, c3.y);
            *(uint4*)(g_kh + (size_t)row * CC + (col - CC)) = *(uint4*)h;
        }
    }
}

// ---------------- Kernel 2: attention scores ----------------
// warp per pixel; lane covers head=lane>>2, dims (lane&3)*8..+8
// one LDG.128/lane per neighbor covers all 8 heads (fp16 k row = 512B)
__global__ __launch_bounds__(256)
void attn_kernel(const float* __restrict__ flows, float* __restrict__ out) {
    __shared__ float sbuf[8][HEADS * NNB];

    const int tidx = threadIdx.x;
    const int wid = tidx >> 5;
    const int lane = tidx & 31;

    const int t = blockIdx.z;
    const int h = blockIdx.y * 4 + (wid >> 1);
    const int w = blockIdx.x * 2 + (wid & 1);
    const int hw = h * WW + w;
    const int pix = t * (HH * WW) + hw;

    const float* qrow = g_q + (size_t)pix * CC;
    const float4 qa = ((const float4*)qrow)[lane * 2];
    const float4 qb = ((const float4*)qrow)[lane * 2 + 1];

    const int tp1 = (t + 1 < TT) ? t + 1 : t - 2;
    const int tp2 = (t - 1 >= 0) ? t - 1 : t + 2;

    const float f10 = flows[(4 * t + 0) * 4096 + hw];
    const float f11 = flows[(4 * t + 1) * 4096 + hw];
    const float f20 = flows[(4 * t + 2) * 4096 + hw];
    const float f21 = flows[(4 * t + 3) * 4096 + hw];

    const int tpr[3] = {t, tp1, tp2};
    const int dii[3] = {0, __float2int_rn(f10), __float2int_rn(f20)};
    const int djj[3] = {0, __float2int_rn(f11), __float2int_rn(f21)};

    float* srow = sbuf[wid];

#pragma unroll
    for (int s = 0; s < 3; s++) {
        const __half* tslice = g_kh + (size_t)tpr[s] * (HH * WW) * CC;
        const int ci = h + dii[s];
        const int cj = w + djj[s];
        int ljo[WS];
#pragma unroll
        for (int b = 0; b < WS; b++) ljo[b] = reflect_idx(cj + b - 3) * CC;

        for (int a = 0; a < WS; a++) {
            const int li = reflect_idx(ci + a - 3);
            const __half* rbase = tslice + (size_t)li * WW * CC;
#pragma unroll
            for (int b = 0; b < WS; b++) {
                const uint4 kv = *(const uint4*)(rbase + ljo[b] + lane * 8);
                const float2 k0 = __half22float2(*reinterpret_cast<const __half2*>(&kv.x));
                const float2 k1 = __half22float2(*reinterpret_cast<const __half2*>(&kv.y));
                const float2 k2 = __half22float2(*reinterpret_cast<const __half2*>(&kv.z));
                const float2 k3 = __half22float2(*reinterpret_cast<const __half2*>(&kv.w));
                float p = qa.x * k0.x;
                p = fmaf(qa.y, k0.y, p);
                p = fmaf(qa.z, k1.x, p);
                p = fmaf(qa.w, k1.y, p);
                p = fmaf(qb.x, k2.x, p);
                p = fmaf(qb.y, k2.y, p);
                p = fmaf(qb.z, k3.x, p);
                p = fmaf(qb.w, k3.y, p);
                p += __shfl_xor_sync(0xffffffffu, p, 1);
                p += __shfl_xor_sync(0xffffffffu, p, 2);
                if ((lane & 3) == 0) {
                    srow[(lane >> 2) * NNB + s * 49 + a * 7 + b] = p;
                }
            }
        }
    }
    __syncwarp();

    const float scale = 0.17677669529663687f;   // 32^-0.5
#pragma unroll
    for (int head = 0; head < HEADS; head++) {
        size_t obase = ((size_t)(head * TT + t) * (HH * WW) + hw) * (size_t)NNB;
        for (int i = lane; i < NNB; i += 32)
            out[obase + i] = srow[head * NNB + i] * scale;
    }
}

// ---------------- Kernel 3: flows_k writer ----------------
__global__ __launch_bounds__(256)
void flowsk_kernel(const float* __restrict__ flows, float* __restrict__ outF) {
    __shared__ float sbuf[8 * NNB * 3];

    const int pix0 = blockIdx.x * 8;
    const int tid = threadIdx.x;

    for (int e = tid; e < 8 * NNB * 3; e += 256) {
        const int lp = e / (NNB * 3);
        const int r = e - lp * (NNB * 3);
        const int n = r / 3;
        const int c = r - n * 3;
        const int pix = pix0 + lp;
        const int t = pix >> 12;
        const int hw = pix & 4095;
        const int h = hw >> 6;
        const int w = hw & 63;

        const int s = n / 49;
        const int wn = n - s * 49;
        const int a = wn / 7;
        const int b = wn - a * 7;

        int dt, di, dj;
        if (s == 0) {
            dt = 0; di = 0; dj = 0;
        } else if (s == 1) {
            dt = (t + 1 < TT) ? 1 : -2;
            di = __float2int_rn(flows[(4 * t + 0) * 4096 + hw]);
            dj = __float2int_rn(flows[(4 * t + 1) * 4096 + hw]);
        } else {
            dt = (t - 1 >= 0) ? -1 : 2;
            di = __float2int_rn(flows[(4 * t + 2) * 4096 + hw]);
            dj = __float2int_rn(flows[(4 * t + 3) * 4096 + hw]);
        }

        int v;
        if (c == 0)      v = dt;
        else if (c == 1) v = reflect_idx(h + di + a - 3) - h;
        else             v = reflect_idx(w + dj + b - 3) - w;
        sbuf[e] = (float)v;
    }
    __syncthreads();

    const float4* s4 = (const float4*)sbuf;
    const int nv4 = (8 * NNB * 3) / 4;
#pragma unroll
    for (int head = 0; head < HEADS; head++) {
        float4* dst = (float4*)(outF + (size_t)head * PER_HEAD_FLOW + (size_t)pix0 * (NNB * 3));
        for (int i = tid; i < nv4; i += 256) dst[i] = s4[i];
    }
}

// ---------------- launch ----------------
extern "C" void kernel_launch(void* const* d_in, const int* in_sizes, int n_in,
                              void* d_out, int out_size) {
    const float* x     = (const float*)d_in[0];
    const float* flows = (const float*)d_in[1];
    const float* Wm    = (const float*)d_in[2];
    float* out = (float*)d_out;

    gemm_qk<<<dim3((2 * CC) / BN, NPIX / BM), 256>>>(x, Wm);
    attn_kernel<<<dim3(WW / 2, HH / 4, TT), 256>>>(flows, out);
    if ((long long)out_size >= (long long)ATTN_ELEMS + (long long)HEADS * PER_HEAD_FLOW) {
        flowsk_kernel<<<NPIX / 8, 256>>>(flows, out + ATTN_ELEMS);
    }
}

// round 5
// speedup vs baseline: 2.7840x; 1.2698x over previous
#include <cuda_runtime.h>
#include <cuda_fp16.h>
#include <cstdint>

// Problem constants
#define TT 8
#define HH 64
#define WW 64
#define CC 256
#define HEADS 8
#define WS 7
#define NNB 147
#define NPIX (TT*HH*WW)                 // 32768
#define ATTN_ELEMS (HEADS*TT*HH*WW*NNB) // 38,535,168
#define PER_HEAD_FLOW (TT*HH*WW*NNB*3)  // 14,450,688
#define NW 512                          // W rows (2*CC)

// Scratch
__device__ float  g_q [(size_t)NPIX * CC];   // q fp32 [pix][256]
__device__ __half g_kh[(size_t)NPIX * CC];   // k fp16 [pix][256]
__device__ __half g_xh[(size_t)NPIX * CC];   // x hi
__device__ __half g_xl[(size_t)NPIX * CC];   // x lo
__device__ __half g_wh[(size_t)NW * CC];     // W hi
__device__ __half g_wl[(size_t)NW * CC];     // W lo

// ---------------- common helpers ----------------
__device__ __forceinline__ int reflect_idx(int idx) {
    int m = idx % 126;
    if (m < 0) m += 126;
    return (m > 63) ? (126 - m) : m;
}

__device__ __forceinline__ uint32_t h2_bits(__half2 v) {
    return *reinterpret_cast<uint32_t*>(&v);
}

__device__ __forceinline__ uint32_t smem_u32(const void* p) {
    uint32_t a;
    asm("{ .reg .u64 t; cvta.to.shared.u64 t, %1; cvt.u32.u64 %0, t; }" : "=r"(a) : "l"(p));
    return a;
}

__device__ __forceinline__ void cp16(uint32_t dst, const void* src) {
    asm volatile("cp.async.ca.shared.global [%0], [%1], 16;" :: "r"(dst), "l"(src));
}
#define CP_COMMIT() asm volatile("cp.async.commit_group;" ::: "memory")
#define CP_WAIT(n)  asm volatile("cp.async.wait_group %0;" :: "n"(n) : "memory")

#define LDSM4(r, a) \
    asm volatile("ldmatrix.sync.aligned.m8n8.x4.shared.b16 {%0,%1,%2,%3}, [%4];" \
                 : "=r"((r)[0]), "=r"((r)[1]), "=r"((r)[2]), "=r"((r)[3]) : "r"(a))

#define MMA16816(d, a, b0, b1) \
    asm volatile("mma.sync.aligned.m16n8k16.row.col.f32.f16.f16.f32 " \
                 "{%0,%1,%2,%3}, {%4,%5,%6,%7}, {%8,%9}, {%0,%1,%2,%3};" \
                 : "+f"((d)[0]), "+f"((d)[1]), "+f"((d)[2]), "+f"((d)[3]) \
                 : "r"((a)[0]), "r"((a)[1]), "r"((a)[2]), "r"((a)[3]), "r"(b0), "r"(b1))

// ---------------- Kernel 0: fp32 -> fp16 hi/lo split ----------------
#define NV4X ((NPIX*CC)/4)   // 2,097,152
#define NV4W ((NW*CC)/4)     // 32,768

__global__ __launch_bounds__(256)
void convert_split(const float* __restrict__ x, const float* __restrict__ Wm) {
    const int total = NV4X + NV4W;
    for (int i = blockIdx.x * blockDim.x + threadIdx.x; i < total; i += gridDim.x * blockDim.x) {
        const float4 v = (i < NV4X) ? ((const float4*)x)[i] : ((const float4*)Wm)[i - NV4X];
        __half2 h01 = __floats2half2_rn(v.x, v.y);
        __half2 h23 = __floats2half2_rn(v.z, v.w);
        float2 r01 = __half22float2(h01);
        float2 r23 = __half22float2(h23);
        __half2 l01 = __floats2half2_rn(v.x - r01.x, v.y - r01.y);
        __half2 l23 = __floats2half2_rn(v.z - r23.x, v.w - r23.y);
        uint2 hv = make_uint2(h2_bits(h01), h2_bits(h23));
        uint2 lv = make_uint2(h2_bits(l01), h2_bits(l23));
        if (i < NV4X) {
            ((uint2*)g_xh)[i] = hv;
            ((uint2*)g_xl)[i] = lv;
        } else {
            ((uint2*)g_wh)[i - NV4X] = hv;
            ((uint2*)g_wl)[i - NV4X] = lv;
        }
    }
}

// ---------------- Kernel 1: HMMA fp16-split GEMM ----------------
// C[m][n] = sum_k x[m][k]*W[n][k]; M=32768, N=512, K=256
// 3-term Markidis: xh*wh + xh*wl + xl*wh, fp32 accum via mma.sync.m16n8k16
#define BM 128
#define BN 128
#define BK 32
#define NIT (CC/BK)                 // 8
#define PADH 40                     // halves per smem row (80B, conflict-free for ldmatrix)
#define TILE_HALVES (128*PADH)      // 5120 halves
#define STAGE_HALVES (4*TILE_HALVES)
#define GSMEM (2*STAGE_HALVES*2)    // 81920 bytes

__device__ __forceinline__ void issue_stage(int it, int stage, int m0, int n0,
                                            uint32_t sbase, int tid) {
    const int kc = it * BK;
    const int r_lo = tid >> 2;            // 0..63
    const int c = (tid & 3) << 3;         // 0,8,16,24
#pragma unroll
    for (int q = 0; q < 8; q++) {
        const int tile = q >> 1;          // 0:xh 1:xl 2:wh 3:wl (uniform)
        const int r = ((q & 1) << 6) + r_lo;   // 0..127
        const __half* src;
        if (tile == 0)      src = g_xh + (size_t)(m0 + r) * CC + kc + c;
        else if (tile == 1) src = g_xl + (size_t)(m0 + r) * CC + kc + c;
        else if (tile == 2) src = g_wh + (size_t)(n0 + r) * CC + kc + c;
        else                src = g_wl + (size_t)(n0 + r) * CC + kc + c;
        const uint32_t dst = sbase +
            (uint32_t)((stage * STAGE_HALVES + tile * TILE_HALVES + r * PADH + c) * 2);
        cp16(dst, src);
    }
}

__global__ __launch_bounds__(256)
void gemm_hmma(void) {
    extern __shared__ __half smem[];
    const uint32_t sbase = smem_u32(smem);
    const int tid = threadIdx.x;
    const int wid = tid >> 5;
    const int lane = tid & 31;

    const int n0 = blockIdx.x * BN;     // 0,128,256,384
    const int m0 = blockIdx.y * BM;
    const bool is_k = (n0 >= CC);

    const int wm = (wid >> 1) * 32;     // warp m offset in tile
    const int wn = (wid & 1) * 64;      // warp n offset in tile
    const int l15 = lane & 15;
    const int kofs = (lane >> 4) << 3;  // 0 or 8

    float acc[2][8][4];
#pragma unroll
    for (int i = 0; i < 2; i++)
#pragma unroll
        for (int j = 0; j < 8; j++)
#pragma unroll
            for (int c = 0; c < 4; c++) acc[i][j][c] = 0.0f;

    issue_stage(0, 0, m0, n0, sbase, tid);
    CP_COMMIT();

    for (int it = 0; it < NIT; it++) {
        if (it + 1 < NIT) {
            issue_stage(it + 1, (it + 1) & 1, m0, n0, sbase, tid);
            CP_COMMIT();
            CP_WAIT(1);
        } else {
            CP_WAIT(0);
        }
        __syncthreads();

        const uint32_t st = sbase + (uint32_t)(((it & 1) * STAGE_HALVES) * 2);
        const uint32_t ah_b = st;
        const uint32_t al_b = st + TILE_HALVES * 2;
        const uint32_t bh_b = st + 2 * TILE_HALVES * 2;
        const uint32_t bl_b = st + 3 * TILE_HALVES * 2;

#pragma unroll
        for (int kk = 0; kk < BK; kk += 16) {
            uint32_t ah[2][4], al[2][4];
#pragma unroll
            for (int mt = 0; mt < 2; mt++) {
                const uint32_t off = (uint32_t)(((wm + mt * 16 + l15) * PADH + kk + kofs) * 2);
                LDSM4(ah[mt], ah_b + off);
                LDSM4(al[mt], al_b + off);
            }
#pragma unroll
            for (int np = 0; np < 4; np++) {
                const uint32_t off = (uint32_t)(((wn + np * 16 + l15) * PADH + kk + kofs) * 2);
                uint32_t bh[4], bl[4];
                LDSM4(bh, bh_b + off);
                LDSM4(bl, bl_b + off);
#pragma unroll
                for (int mt = 0; mt < 2; mt++) {
                    MMA16816(acc[mt][2 * np],     ah[mt], bh[0], bh[2]);
                    MMA16816(acc[mt][2 * np + 1], ah[mt], bh[1], bh[3]);
                    MMA16816(acc[mt][2 * np],     ah[mt], bl[0], bl[2]);
                    MMA16816(acc[mt][2 * np + 1], ah[mt], bl[1], bl[3]);
                    MMA16816(acc[mt][2 * np],     al[mt], bh[0], bh[2]);
                    MMA16816(acc[mt][2 * np + 1], al[mt], bh[1], bh[3]);
                }
            }
        }
        __syncthreads();
    }

    // epilogue: write q (fp32) or k (fp16)
    const int r0 = m0 + wm + (lane >> 2);
    const int cbase = wn + ((lane & 3) << 1);
#pragma unroll
    for (int mt = 0; mt < 2; mt++) {
        const int row0 = r0 + mt * 16;
#pragma unroll
        for (int nt = 0; nt < 8; nt++) {
            const int col = n0 + cbase + nt * 8;
            float* a = acc[mt][nt];
            if (!is_k) {
                *(float2*)(g_q + (size_t)row0 * CC + col)       = make_float2(a[0], a[1]);
                *(float2*)(g_q + (size_t)(row0 + 8) * CC + col) = make_float2(a[2], a[3]);
            } else {
                __half2 h0 = __floats2half2_rn(a[0], a[1]);
                __half2 h1 = __floats2half2_rn(a[2], a[3]);
                *(uint32_t*)(g_kh + (size_t)row0 * CC + (col - CC))       = h2_bits(h0);
                *(uint32_t*)(g_kh + (size_t)(row0 + 8) * CC + (col - CC)) = h2_bits(h1);
            }
        }
    }
}

// ---------------- Kernel 2: attention scores ----------------
__global__ __launch_bounds__(256)
void attn_kernel(const float* __restrict__ flows, float* __restrict__ out) {
    __shared__ float sbuf[8][HEADS * NNB];

    const int tidx = threadIdx.x;
    const int wid = tidx >> 5;
    const int lane = tidx & 31;

    const int t = blockIdx.z;
    const int h = blockIdx.y * 4 + (wid >> 1);
    const int w = blockIdx.x * 2 + (wid & 1);
    const int hw = h * WW + w;
    const int pix = t * (HH * WW) + hw;

    const float* qrow = g_q + (size_t)pix * CC;
    const float4 qa = ((const float4*)qrow)[lane * 2];
    const float4 qb = ((const float4*)qrow)[lane * 2 + 1];

    const int tp1 = (t + 1 < TT) ? t + 1 : t - 2;
    const int tp2 = (t - 1 >= 0) ? t - 1 : t + 2;

    const float f10 = flows[(4 * t + 0) * 4096 + hw];
    const float f11 = flows[(4 * t + 1) * 4096 + hw];
    const float f20 = flows[(4 * t + 2) * 4096 + hw];
    const float f21 = flows[(4 * t + 3) * 4096 + hw];

    const int tpr[3] = {t, tp1, tp2};
    const int dii[3] = {0, __float2int_rn(f10), __float2int_rn(f20)};
    const int djj[3] = {0, __float2int_rn(f11), __float2int_rn(f21)};

    float* srow = sbuf[wid];

#pragma unroll
    for (int s = 0; s < 3; s++) {
        const __half* tslice = g_kh + (size_t)tpr[s] * (HH * WW) * CC;
        const int ci = h + dii[s];
        const int cj = w + djj[s];
        int ljo[WS];
#pragma unroll
        for (int b = 0; b < WS; b++) ljo[b] = reflect_idx(cj + b - 3) * CC;

        for (int a = 0; a < WS; a++) {
            const int li = reflect_idx(ci + a - 3);
            const __half* rbase = tslice + (size_t)li * WW * CC;
#pragma unroll
            for (int b = 0; b < WS; b++) {
                const uint4 kv = *(const uint4*)(rbase + ljo[b] + lane * 8);
                const float2 k0 = __half22float2(*reinterpret_cast<const __half2*>(&kv.x));
                const float2 k1 = __half22float2(*reinterpret_cast<const __half2*>(&kv.y));
                const float2 k2 = __half22float2(*reinterpret_cast<const __half2*>(&kv.z));
                const float2 k3 = __half22float2(*reinterpret_cast<const __half2*>(&kv.w));
                float p = qa.x * k0.x;
                p = fmaf(qa.y, k0.y, p);
                p = fmaf(qa.z, k1.x, p);
                p = fmaf(qa.w, k1.y, p);
                p = fmaf(qb.x, k2.x, p);
                p = fmaf(qb.y, k2.y, p);
                p = fmaf(qb.z, k3.x, p);
                p = fmaf(qb.w, k3.y, p);
                p += __shfl_xor_sync(0xffffffffu, p, 1);
                p += __shfl_xor_sync(0xffffffffu, p, 2);
                if ((lane & 3) == 0) {
                    srow[(lane >> 2) * NNB + s * 49 + a * 7 + b] = p;
                }
            }
        }
    }
    __syncwarp();

    const float scale = 0.17677669529663687f;
#pragma unroll
    for (int head = 0; head < HEADS; head++) {
        size_t obase = ((size_t)(head * TT + t) * (HH * WW) + hw) * (size_t)NNB;
        for (int i = lane; i < NNB; i += 32)
            out[obase + i] = srow[head * NNB + i] * scale;
    }
}

// ---------------- Kernel 3: flows_k writer ----------------
__global__ __launch_bounds__(256)
void flowsk_kernel(const float* __restrict__ flows, float* __restrict__ outF) {
    __shared__ float sbuf[8 * NNB * 3];

    const int pix0 = blockIdx.x * 8;
    const int tid = threadIdx.x;

    for (int e = tid; e < 8 * NNB * 3; e += 256) {
        const int lp = e / (NNB * 3);
        const int r = e - lp * (NNB * 3);
        const int n = r / 3;
        const int c = r - n * 3;
        const int pix = pix0 + lp;
        const int t = pix >> 12;
        const int hw = pix & 4095;
        const int h = hw >> 6;
        const int w = hw & 63;

        const int s = n / 49;
        const int wn = n - s * 49;
        const int a = wn / 7;
        const int b = wn - a * 7;

        int dt, di, dj;
        if (s == 0) {
            dt = 0; di = 0; dj = 0;
        } else if (s == 1) {
            dt = (t + 1 < TT) ? 1 : -2;
            di = __float2int_rn(flows[(4 * t + 0) * 4096 + hw]);
            dj = __float2int_rn(flows[(4 * t + 1) * 4096 + hw]);
        } else {
            dt = (t - 1 >= 0) ? -1 : 2;
            di = __float2int_rn(flows[(4 * t + 2) * 4096 + hw]);
            dj = __float2int_rn(flows[(4 * t + 3) * 4096 + hw]);
        }

        int v;
        if (c == 0)      v = dt;
        else if (c == 1) v = reflect_idx(h + di + a - 3) - h;
        else             v = reflect_idx(w + dj + b - 3) - w;
        sbuf[e] = (float)v;
    }
    __syncthreads();

    const float4* s4 = (const float4*)sbuf;
    const int nv4 = (8 * NNB * 3) / 4;
#pragma unroll
    for (int head = 0; head < HEADS; head++) {
        float4* dst = (float4*)(outF + (size_t)head * PER_HEAD_FLOW + (size_t)pix0 * (NNB * 3));
        for (int i = tid; i < nv4; i += 256) dst[i] = s4[i];
    }
}

// ---------------- launch ----------------
extern "C" void kernel_launch(void* const* d_in, const int* in_sizes, int n_in,
                              void* d_out, int out_size) {
    const float* x     = (const float*)d_in[0];
    const float* flows = (const float*)d_in[1];
    const float* Wm    = (const float*)d_in[2];
    float* out = (float*)d_out;

    cudaFuncSetAttribute(gemm_hmma, cudaFuncAttributeMaxDynamicSharedMemorySize, GSMEM);

    convert_split<<<1184, 256>>>(x, Wm);
    gemm_hmma<<<dim3(NW / BN, NPIX / BM), 256, GSMEM>>>();
    attn_kernel<<<dim3(WW / 2, HH / 4, TT), 256>>>(flows, out);
    if ((long long)out_size >= (long long)ATTN_ELEMS + (long long)HEADS * PER_HEAD_FLOW) {
        flowsk_kernel<<<NPIX / 8, 256>>>(flows, out + ATTN_ELEMS);
    }
}

// round 9
// speedup vs baseline: 2.8660x; 1.0294x over previous
#include <cuda_runtime.h>
#include <cuda_fp16.h>
#include <cstdint>

// Problem constants
#define TT 8
#define HH 64
#define WW 64
#define CC 256
#define HEADS 8
#define WS 7
#define NNB 147
#define NPIX (TT*HH*WW)                 // 32768
#define ATTN_ELEMS (HEADS*TT*HH*WW*NNB) // 38,535,168
#define PER_HEAD_FLOW (TT*HH*WW*NNB*3)  // 14,450,688
#define NW 512                          // W rows (2*CC)

// Scratch
__device__ float  g_q [(size_t)NPIX * CC];   // q fp32 [pix][256]
__device__ __half g_kh[(size_t)NPIX * CC];   // k fp16 [pix][256]
__device__ __half g_xh[(size_t)NPIX * CC];   // x hi
__device__ __half g_xl[(size_t)NPIX * CC];   // x lo
__device__ __half g_wh[(size_t)NW * CC];     // W hi
__device__ __half g_wl[(size_t)NW * CC];     // W lo

// ---------------- common helpers ----------------
__device__ __forceinline__ int reflect_idx(int idx) {
    int m = idx % 126;
    if (m < 0) m += 126;
    return (m > 63) ? (126 - m) : m;
}

__device__ __forceinline__ uint32_t h2_bits(__half2 v) {
    return *reinterpret_cast<uint32_t*>(&v);
}

__device__ __forceinline__ uint32_t smem_u32(const void* p) {
    uint32_t a;
    asm("{ .reg .u64 t; cvta.to.shared.u64 t, %1; cvt.u32.u64 %0, t; }" : "=r"(a) : "l"(p));
    return a;
}

__device__ __forceinline__ void cp16(uint32_t dst, const void* src) {
    asm volatile("cp.async.ca.shared.global [%0], [%1], 16;" :: "r"(dst), "l"(src));
}
#define CP_COMMIT() asm volatile("cp.async.commit_group;" ::: "memory")
#define CP_WAIT(n)  asm volatile("cp.async.wait_group %0;" :: "n"(n) : "memory")

#define LDSM4(r, a) \
    asm volatile("ldmatrix.sync.aligned.m8n8.x4.shared.b16 {%0,%1,%2,%3}, [%4];" \
                 : "=r"((r)[0]), "=r"((r)[1]), "=r"((r)[2]), "=r"((r)[3]) : "r"(a))

#define MMA16816(d, a, b0, b1) \
    asm volatile("mma.sync.aligned.m16n8k16.row.col.f32.f16.f16.f32 " \
                 "{%0,%1,%2,%3}, {%4,%5,%6,%7}, {%8,%9}, {%0,%1,%2,%3};" \
                 : "+f"((d)[0]), "+f"((d)[1]), "+f"((d)[2]), "+f"((d)[3]) \
                 : "r"((a)[0]), "r"((a)[1]), "r"((a)[2]), "r"((a)[3]), "r"(b0), "r"(b1))

// ---------------- Kernel 0: fp32 -> fp16 hi/lo split ----------------
#define NV4X ((NPIX*CC)/4)   // 2,097,152
#define NV4W ((NW*CC)/4)     // 32,768

__global__ __launch_bounds__(256)
void convert_split(const float* __restrict__ x, const float* __restrict__ Wm) {
    const int total = NV4X + NV4W;
    for (int i = blockIdx.x * blockDim.x + threadIdx.x; i < total; i += gridDim.x * blockDim.x) {
        const float4 v = (i < NV4X) ? ((const float4*)x)[i] : ((const float4*)Wm)[i - NV4X];
        __half2 h01 = __floats2half2_rn(v.x, v.y);
        __half2 h23 = __floats2half2_rn(v.z, v.w);
        float2 r01 = __half22float2(h01);
        float2 r23 = __half22float2(h23);
        __half2 l01 = __floats2half2_rn(v.x - r01.x, v.y - r01.y);
        __half2 l23 = __floats2half2_rn(v.z - r23.x, v.w - r23.y);
        uint2 hv = make_uint2(h2_bits(h01), h2_bits(h23));
        uint2 lv = make_uint2(h2_bits(l01), h2_bits(l23));
        if (i < NV4X) {
            ((uint2*)g_xh)[i] = hv;
            ((uint2*)g_xl)[i] = lv;
        } else {
            ((uint2*)g_wh)[i - NV4X] = hv;
            ((uint2*)g_wl)[i - NV4X] = lv;
        }
    }
}

// ---------------- Kernel 1: HMMA fp16-split GEMM ----------------
#define BM 128
#define BN 128
#define BK 32
#define NIT (CC/BK)                 // 8
#define PADH 40                     // halves per smem row (80B)
#define TILE_HALVES (128*PADH)
#define STAGE_HALVES (4*TILE_HALVES)
#define GSMEM (2*STAGE_HALVES*2)    // 81920 bytes

__device__ __forceinline__ void issue_stage(int it, int stage, int m0, int n0,
                                            uint32_t sbase, int tid) {
    const int kc = it * BK;
    const int r_lo = tid >> 2;
    const int c = (tid & 3) << 3;
#pragma unroll
    for (int q = 0; q < 8; q++) {
        const int tile = q >> 1;
        const int r = ((q & 1) << 6) + r_lo;
        const __half* src;
        if (tile == 0)      src = g_xh + (size_t)(m0 + r) * CC + kc + c;
        else if (tile == 1) src = g_xl + (size_t)(m0 + r) * CC + kc + c;
        else if (tile == 2) src = g_wh + (size_t)(n0 + r) * CC + kc + c;
        else                src = g_wl + (size_t)(n0 + r) * CC + kc + c;
        const uint32_t dst = sbase +
            (uint32_t)((stage * STAGE_HALVES + tile * TILE_HALVES + r * PADH + c) * 2);
        cp16(dst, src);
    }
}

__global__ __launch_bounds__(256)
void gemm_hmma(void) {
    extern __shared__ __half smem[];
    const uint32_t sbase = smem_u32(smem);
    const int tid = threadIdx.x;
    const int wid = tid >> 5;
    const int lane = tid & 31;

    const int n0 = blockIdx.x * BN;
    const int m0 = blockIdx.y * BM;
    const bool is_k = (n0 >= CC);

    const int wm = (wid >> 1) * 32;
    const int wn = (wid & 1) * 64;
    const int l15 = lane & 15;
    const int kofs = (lane >> 4) << 3;

    float acc[2][8][4];
#pragma unroll
    for (int i = 0; i < 2; i++)
#pragma unroll
        for (int j = 0; j < 8; j++)
#pragma unroll
            for (int c = 0; c < 4; c++) acc[i][j][c] = 0.0f;

    issue_stage(0, 0, m0, n0, sbase, tid);
    CP_COMMIT();

    for (int it = 0; it < NIT; it++) {
        if (it + 1 < NIT) {
            issue_stage(it + 1, (it + 1) & 1, m0, n0, sbase, tid);
            CP_COMMIT();
            CP_WAIT(1);
        } else {
            CP_WAIT(0);
        }
        __syncthreads();

        const uint32_t st = sbase + (uint32_t)(((it & 1) * STAGE_HALVES) * 2);
        const uint32_t ah_b = st;
        const uint32_t al_b = st + TILE_HALVES * 2;
        const uint32_t bh_b = st + 2 * TILE_HALVES * 2;
        const uint32_t bl_b = st + 3 * TILE_HALVES * 2;

#pragma unroll
        for (int kk = 0; kk < BK; kk += 16) {
            uint32_t ah[2][4], al[2][4];
#pragma unroll
            for (int mt = 0; mt < 2; mt++) {
                const uint32_t off = (uint32_t)(((wm + mt * 16 + l15) * PADH + kk + kofs) * 2);
                LDSM4(ah[mt], ah_b + off);
                LDSM4(al[mt], al_b + off);
            }
#pragma unroll
            for (int np = 0; np < 4; np++) {
                const uint32_t off = (uint32_t)(((wn + np * 16 + l15) * PADH + kk + kofs) * 2);
                uint32_t bh[4], bl[4];
                LDSM4(bh, bh_b + off);
                LDSM4(bl, bl_b + off);
#pragma unroll
                for (int mt = 0; mt < 2; mt++) {
                    MMA16816(acc[mt][2 * np],     ah[mt], bh[0], bh[2]);
                    MMA16816(acc[mt][2 * np + 1], ah[mt], bh[1], bh[3]);
                    MMA16816(acc[mt][2 * np],     ah[mt], bl[0], bl[2]);
                    MMA16816(acc[mt][2 * np + 1], ah[mt], bl[1], bl[3]);
                    MMA16816(acc[mt][2 * np],     al[mt], bh[0], bh[2]);
                    MMA16816(acc[mt][2 * np + 1], al[mt], bh[1], bh[3]);
                }
            }
        }
        __syncthreads();
    }

    const int r0 = m0 + wm + (lane >> 2);
    const int cbase = wn + ((lane & 3) << 1);
#pragma unroll
    for (int mt = 0; mt < 2; mt++) {
        const int row0 = r0 + mt * 16;
#pragma unroll
        for (int nt = 0; nt < 8; nt++) {
            const int col = n0 + cbase + nt * 8;
            float* a = acc[mt][nt];
            if (!is_k) {
                *(float2*)(g_q + (size_t)row0 * CC + col)       = make_float2(a[0], a[1]);
                *(float2*)(g_q + (size_t)(row0 + 8) * CC + col) = make_float2(a[2], a[3]);
            } else {
                __half2 h0 = __floats2half2_rn(a[0], a[1]);
                __half2 h1 = __floats2half2_rn(a[2], a[3]);
                *(uint32_t*)(g_kh + (size_t)row0 * CC + (col - CC))       = h2_bits(h0);
                *(uint32_t*)(g_kh + (size_t)(row0 + 8) * CC + (col - CC)) = h2_bits(h1);
            }
        }
    }
}

// ---------------- Kernel 2: attention scores + flows_k writes ----------------
#define WBUF 1344   // per-warp smem floats (scores 1176 / flow expansion <=448+pad, reused)

__global__ __launch_bounds__(256)
void attn_kernel(const float* __restrict__ flows, float* __restrict__ out) {
    __shared__ float sbuf[8 * WBUF];
    __shared__ float mtab[8 * 48];   // per-warp mini tables: dt[3], diR[21], djR[21]

    const int tidx = threadIdx.x;
    const int wid = tidx >> 5;
    const int lane = tidx & 31;

    const int t = blockIdx.z;
    const int h = blockIdx.y * 4 + (wid >> 1);
    const int w = blockIdx.x * 2 + (wid & 1);
    const int hw = h * WW + w;
    const int pix = t * (HH * WW) + hw;

    const float* qrow = g_q + (size_t)pix * CC;
    const float4 qa = ((const float4*)qrow)[lane * 2];
    const float4 qb = ((const float4*)qrow)[lane * 2 + 1];

    const int tp1 = (t + 1 < TT) ? t + 1 : t - 2;
    const int tp2 = (t - 1 >= 0) ? t - 1 : t + 2;

    const float f10 = flows[(4 * t + 0) * 4096 + hw];
    const float f11 = flows[(4 * t + 1) * 4096 + hw];
    const float f20 = flows[(4 * t + 2) * 4096 + hw];
    const float f21 = flows[(4 * t + 3) * 4096 + hw];

    const int di1 = __float2int_rn(f10), dj1 = __float2int_rn(f11);
    const int di2 = __float2int_rn(f20), dj2 = __float2int_rn(f21);

    const int tpr[3] = {t, tp1, tp2};
    const int dii[3] = {0, di1, di2};
    const int djj[3] = {0, dj1, dj2};

    float* srow = sbuf + wid * WBUF;
    float* mt = mtab + wid * 48;

    // ---- fill per-pixel mini tables (45 values; strided over 32 lanes!) ----
    for (int idx = lane; idx < 45; idx += 32) {
        float v;
        if (idx < 3) {
            const int dtv = (idx == 0) ? 0 : (idx == 1 ? ((t + 1 < TT) ? 1 : -2)
                                                       : ((t - 1 >= 0) ? -1 : 2));
            v = (float)dtv;
        } else if (idx < 24) {
            const int l = idx - 3;
            const int s = l / 7, a = l - s * 7;
            const int ds = (s == 0) ? 0 : (s == 1 ? di1 : di2);
            v = (float)(reflect_idx(h + ds + a - 3) - h);
        } else {
            const int l = idx - 24;
            const int s = l / 7, b = l - s * 7;
            const int ds = (s == 0) ? 0 : (s == 1 ? dj1 : dj2);
            v = (float)(reflect_idx(w + ds + b - 3) - w);
        }
        mt[idx] = v;
    }

    // ---- scores ----
#pragma unroll
    for (int s = 0; s < 3; s++) {
        const __half* tslice = g_kh + (size_t)tpr[s] * (HH * WW) * CC;
        const int ci = h + dii[s];
        const int cj = w + djj[s];
        int ljo[WS];
#pragma unroll
        for (int b = 0; b < WS; b++) ljo[b] = reflect_idx(cj + b - 3) * CC;

        for (int a = 0; a < WS; a++) {
            const int li = reflect_idx(ci + a - 3);
            const __half* rbase = tslice + (size_t)li * WW * CC;
#pragma unroll
            for (int b = 0; b < WS; b++) {
                const uint4 kv = *(const uint4*)(rbase + ljo[b] + lane * 8);
                const float2 k0 = __half22float2(*reinterpret_cast<const __half2*>(&kv.x));
                const float2 k1 = __half22float2(*reinterpret_cast<const __half2*>(&kv.y));
                const float2 k2 = __half22float2(*reinterpret_cast<const __half2*>(&kv.z));
                const float2 k3 = __half22float2(*reinterpret_cast<const __half2*>(&kv.w));
                float p = qa.x * k0.x;
                p = fmaf(qa.y, k0.y, p);
                p = fmaf(qa.z, k1.x, p);
                p = fmaf(qa.w, k1.y, p);
                p = fmaf(qb.x, k2.x, p);
                p = fmaf(qb.y, k2.y, p);
                p = fmaf(qb.z, k3.x, p);
                p = fmaf(qb.w, k3.y, p);
                p += __shfl_xor_sync(0xffffffffu, p, 1);
                p += __shfl_xor_sync(0xffffffffu, p, 2);
                if ((lane & 3) == 0) {
                    srow[(lane >> 2) * NNB + s * 49 + a * 7 + b] = p;
                }
            }
        }
    }
    __syncwarp();

    const float scale = 0.17677669529663687f;
#pragma unroll
    for (int head = 0; head < HEADS; head++) {
        size_t obase = ((size_t)(head * TT + t) * (HH * WW) + hw) * (size_t)NNB;
        for (int i = lane; i < NNB; i += 32)
            out[obase + i] = srow[head * NNB + i] * scale;
    }
    __syncwarp();

    // ---- flows_k: expand mini tables into srow (reused), then replicate x8 ----
    const int basef = pix * (NNB * 3);       // float offset within a head slab
    const int pad = basef & 3;               // store element e at srow[pad+e]
    for (int n = lane; n < NNB; n += 32) {
        const int s = (n >= 98) ? 2 : ((n >= 49) ? 1 : 0);
        const int r = n - s * 49;
        const int a = r / 7;
        const int b = r - a * 7;
        const int o = pad + 3 * n;
        srow[o]     = mt[s];
        srow[o + 1] = mt[3 + s * 7 + a];
        srow[o + 2] = mt[24 + s * 7 + b];
    }
    __syncwarp();

    float* outF = out + (size_t)ATTN_ELEMS;
    const int lead = (4 - pad) & 3;
    const int nv4 = (NNB * 3 - lead) >> 2;
    const int tail = (NNB * 3 - lead) & 3;
    const float4* s4 = (const float4*)(srow + pad + lead);
#pragma unroll
    for (int head = 0; head < HEADS; head++) {
        float* gp = outF + (size_t)head * PER_HEAD_FLOW + basef;
        if (lane < lead) gp[lane] = srow[pad + lane];
        float4* g4 = (float4*)(gp + lead);
        for (int i = lane; i < nv4; i += 32) g4[i] = s4[i];
        if (lane < tail) gp[lead + 4 * nv4 + lane] = srow[pad + lead + 4 * nv4 + lane];
    }
}

// ---------------- launch ----------------
extern "C" void kernel_launch(void* const* d_in, const int* in_sizes, int n_in,
                              void* d_out, int out_size) {
    const float* x     = (const float*)d_in[0];
    const float* flows = (const float*)d_in[1];
    const float* Wm    = (const float*)d_in[2];
    float* out = (float*)d_out;

    cudaFuncSetAttribute(gemm_hmma, cudaFuncAttributeMaxDynamicSharedMemorySize, GSMEM);

    convert_split<<<1184, 256>>>(x, Wm);
    gemm_hmma<<<dim3(NW / BN, NPIX / BM), 256, GSMEM>>>();
    attn_kernel<<<dim3(WW / 2, HH / 4, TT), 256>>>(flows, out);
}